// round 1
// baseline (speedup 1.0000x reference)
#include <cuda_runtime.h>

#define BB 64
#define SS 4096
#define DD 64
#define FF 256

#define INV_SIGMA 0.3535533905932738f   /* 64^-0.25 = 2^-1.5 */
#define INV_SQRT_F 0.0625f              /* 256^-0.5 */
#define TS_KM 256
#define TS_KV 256
#define TS_OUT 32

// ---------------- scratch (device globals: no allocation allowed) ----------
__device__ float        g_mean[BB * DD];        // raw sums of k over S
__device__ float        g_kv  [BB * FF * DD];   // sum_s phi_k[s,f] * v[s,d]
__device__ float        g_ksum[BB * FF];        // sum_s phi_k[s,f]
__device__ unsigned int g_kmax[BB];             // ordered-uint encoded max

typedef unsigned long long u64;

// ---------------- packed f32x2 helpers (FFMA2 path) ------------------------
__device__ __forceinline__ u64 pk2(float lo, float hi) {
    u64 r; asm("mov.b64 %0,{%1,%2};" : "=l"(r) : "f"(lo), "f"(hi)); return r;
}
__device__ __forceinline__ float2 upk2(u64 v) {
    float2 r; asm("mov.b64 {%0,%1},%2;" : "=f"(r.x), "=f"(r.y) : "l"(v)); return r;
}
__device__ __forceinline__ u64 fma2(u64 a, u64 b, u64 c) {
    u64 d; asm("fma.rn.f32x2 %0,%1,%2,%3;" : "=l"(d) : "l"(a), "l"(b), "l"(c)); return d;
}

// ordered-uint encoding for float atomicMax (monotonic for all finite + inf)
__device__ __forceinline__ unsigned enc_max(float x) {
    unsigned b = __float_as_uint(x);
    return (b & 0x80000000u) ? ~b : (b | 0x80000000u);
}
__device__ __forceinline__ float dec_max(unsigned k) {
    return (k & 0x80000000u) ? __uint_as_float(k & 0x7FFFFFFFu)
                             : __uint_as_float(~k);
}

// dot(row[0:64], Wrow) with packed fma, row must be 16B-aligned smem
__device__ __forceinline__ float proj_row(const float* row, const u64* w2) {
    const ulonglong2* kr = (const ulonglong2*)row;
    u64 a0 = 0ull, a1 = 0ull;
#pragma unroll
    for (int i = 0; i < 16; i++) {
        ulonglong2 kk = kr[i];
        a0 = fma2(kk.x, w2[2 * i],     a0);
        a1 = fma2(kk.y, w2[2 * i + 1], a1);
    }
    float2 x = upk2(a0), y = upk2(a1);
    return (x.x + x.y) + (y.x + y.y);
}

__device__ __forceinline__ void load_w_regs(const float* __restrict__ w, int f, u64* w2) {
    const float4* wr = (const float4*)(w + f * DD);
#pragma unroll
    for (int i = 0; i < 16; i++) {
        float4 t = wr[i];
        w2[2 * i]     = pk2(t.x, t.y);
        w2[2 * i + 1] = pk2(t.z, t.w);
    }
}

// ---------------- kernel 0: init scratch ------------------------------------
__global__ void init_kernel() {
    int i = blockIdx.x * 256 + threadIdx.x;
    if (i < BB * FF * DD) g_kv[i]   = 0.0f;
    if (i < BB * FF)      g_ksum[i] = 0.0f;
    if (i < BB * DD)      g_mean[i] = 0.0f;
    if (i < BB)           g_kmax[i] = 0x007FFFFFu;  // enc(-inf)
}

// ---------------- kernel 1: per-(b,d) sum of k over S -----------------------
__global__ void mean_kernel(const float* __restrict__ k) {
    const int b = blockIdx.x;
    const int p = blockIdx.y;                 // 4 S-partitions
    const int d   = threadIdx.x & 63;
    const int sub = threadIdx.x >> 6;         // 0..3
    const float* kp = k + (b * SS + p * 1024) * DD;
    float s = 0.0f;
    for (int r = sub; r < 1024; r += 4) s += kp[r * DD + d];
    __shared__ float sm[4][DD];
    sm[sub][d] = s;
    __syncthreads();
    if (threadIdx.x < DD) {
        float t = sm[0][threadIdx.x] + sm[1][threadIdx.x] +
                  sm[2][threadIdx.x] + sm[3][threadIdx.x];
        atomicAdd(&g_mean[b * DD + threadIdx.x], t);
    }
}

// ---------------- kernel 2: global max of centered-K projection -------------
__global__ void __launch_bounds__(256, 2)
kmax_kernel(const float* __restrict__ k, const float* __restrict__ w) {
    const int b = blockIdx.x, tile = blockIdx.y;
    const int f = threadIdx.x;
    u64 w2[32];
    load_w_regs(w, f, w2);

    __shared__ float meanc[DD];
    __shared__ __align__(16) float kc[16][DD];
    __shared__ float wred[8];
    if (threadIdx.x < DD)
        meanc[threadIdx.x] = g_mean[b * DD + threadIdx.x] * (INV_SIGMA / (float)SS);
    __syncthreads();

    float m = -3.0e38f;
    const float* kb = k + (b * SS + tile * TS_KM) * DD;
    for (int c = 0; c < TS_KM / 16; c++) {
        {
            const int r = threadIdx.x >> 4, seg = threadIdx.x & 15;
            const int off = (c * 16 + r) * DD + seg * 4;
            float4 kk = *(const float4*)(kb + off);
            float4 cc;
            cc.x = kk.x * INV_SIGMA - meanc[seg * 4 + 0];
            cc.y = kk.y * INV_SIGMA - meanc[seg * 4 + 1];
            cc.z = kk.z * INV_SIGMA - meanc[seg * 4 + 2];
            cc.w = kk.w * INV_SIGMA - meanc[seg * 4 + 3];
            *(float4*)&kc[r][seg * 4] = cc;
        }
        __syncthreads();
#pragma unroll 1
        for (int r = 0; r < 16; r++) m = fmaxf(m, proj_row(kc[r], w2));
        __syncthreads();
    }
    // block max
    m = fmaxf(m, __shfl_xor_sync(0xffffffffu, m, 16));
    m = fmaxf(m, __shfl_xor_sync(0xffffffffu, m, 8));
    m = fmaxf(m, __shfl_xor_sync(0xffffffffu, m, 4));
    m = fmaxf(m, __shfl_xor_sync(0xffffffffu, m, 2));
    m = fmaxf(m, __shfl_xor_sync(0xffffffffu, m, 1));
    if ((threadIdx.x & 31) == 0) wred[threadIdx.x >> 5] = m;
    __syncthreads();
    if (threadIdx.x == 0) {
        float mm = wred[0];
#pragma unroll
        for (int i = 1; i < 8; i++) mm = fmaxf(mm, wred[i]);
        atomicMax(&g_kmax[b], enc_max(mm));
    }
}

// ---------------- kernel 3: kv = phi_k^T @ V, ksum = sum phi_k --------------
__global__ void __launch_bounds__(256, 1)
kv_kernel(const float* __restrict__ k, const float* __restrict__ v,
          const float* __restrict__ w) {
    const int b = blockIdx.x, tile = blockIdx.y;
    const int f = threadIdx.x;
    u64 w2[32];
    load_w_regs(w, f, w2);

    __shared__ float meanc[DD];
    __shared__ __align__(16) float kc[16][DD];
    __shared__ __align__(16) float vv[16][DD];
    __shared__ float nsq[16];
    if (threadIdx.x < DD)
        meanc[threadIdx.x] = g_mean[b * DD + threadIdx.x] * (INV_SIGMA / (float)SS);
    const float gmax = dec_max(g_kmax[b]);

    u64 kv2[32];
#pragma unroll
    for (int j = 0; j < 32; j++) kv2[j] = 0ull;
    float ksum = 0.0f;
    __syncthreads();

    const float* kb = k + (b * SS + tile * TS_KV) * DD;
    const float* vb = v + (b * SS + tile * TS_KV) * DD;
    for (int c = 0; c < TS_KV / 16; c++) {
        {
            const int r = threadIdx.x >> 4, seg = threadIdx.x & 15;
            const int off = (c * 16 + r) * DD + seg * 4;
            float4 kk = *(const float4*)(kb + off);
            float4 cc;
            cc.x = kk.x * INV_SIGMA - meanc[seg * 4 + 0];
            cc.y = kk.y * INV_SIGMA - meanc[seg * 4 + 1];
            cc.z = kk.z * INV_SIGMA - meanc[seg * 4 + 2];
            cc.w = kk.w * INV_SIGMA - meanc[seg * 4 + 3];
            *(float4*)&kc[r][seg * 4] = cc;
            *(float4*)&vv[r][seg * 4] = *(const float4*)(vb + off);
            float sq = cc.x * cc.x + cc.y * cc.y + cc.z * cc.z + cc.w * cc.w;
            sq += __shfl_xor_sync(0xffffffffu, sq, 1);
            sq += __shfl_xor_sync(0xffffffffu, sq, 2);
            sq += __shfl_xor_sync(0xffffffffu, sq, 4);
            sq += __shfl_xor_sync(0xffffffffu, sq, 8);
            if (seg == 0) nsq[r] = 0.5f * sq;
        }
        __syncthreads();
#pragma unroll 1
        for (int r = 0; r < 16; r++) {
            float kp  = proj_row(kc[r], w2);
            float phi = __expf(kp - nsq[r] - gmax) * INV_SQRT_F;
            ksum += phi;
            u64 p2 = pk2(phi, phi);
            const ulonglong2* vr = (const ulonglong2*)vv[r];
#pragma unroll
            for (int j = 0; j < 16; j++) {
                ulonglong2 vq = vr[j];
                kv2[2 * j]     = fma2(p2, vq.x, kv2[2 * j]);
                kv2[2 * j + 1] = fma2(p2, vq.y, kv2[2 * j + 1]);
            }
        }
        __syncthreads();
    }
    atomicAdd(&g_ksum[b * FF + f], ksum);
    float* dst = g_kv + (b * FF + f) * DD;
#pragma unroll
    for (int j = 0; j < 32; j++) {
        float2 p = upk2(kv2[j]);
        atomicAdd(dst + 2 * j,     p.x);
        atomicAdd(dst + 2 * j + 1, p.y);
    }
}

// ---------------- kernel 4: phi_q, deno, out = phi_q @ kv / deno ------------
__global__ void __launch_bounds__(256, 2)
out_kernel(const float* __restrict__ q, const float* __restrict__ w,
           float* __restrict__ out) {
    const int b = blockIdx.x;
    const int tile = blockIdx.y;   // S / TS_OUT tiles
    const int f = threadIdx.x;
    u64 w2[32];
    load_w_regs(w, f, w2);

    __shared__ float phi[TS_OUT][FF + 1];
    __shared__ __align__(16) float qs[TS_OUT][DD];
    __shared__ __align__(16) float kvs[16][DD];
    __shared__ float ksum_s[FF];
    __shared__ float nsq[TS_OUT], mrow[TS_OUT], dens[TS_OUT];

    ksum_s[f] = g_ksum[b * FF + f];
    {
        const int r = threadIdx.x >> 3, seg = threadIdx.x & 7;
        const float4* src = (const float4*)(q + (b * SS + tile * TS_OUT + r) * DD + seg * 8);
        float4 a = src[0], c = src[1];
        a.x *= INV_SIGMA; a.y *= INV_SIGMA; a.z *= INV_SIGMA; a.w *= INV_SIGMA;
        c.x *= INV_SIGMA; c.y *= INV_SIGMA; c.z *= INV_SIGMA; c.w *= INV_SIGMA;
        *(float4*)&qs[r][seg * 8]     = a;
        *(float4*)&qs[r][seg * 8 + 4] = c;
        float sq = a.x * a.x + a.y * a.y + a.z * a.z + a.w * a.w +
                   c.x * c.x + c.y * c.y + c.z * c.z + c.w * c.w;
        sq += __shfl_xor_sync(0xffffffffu, sq, 1);
        sq += __shfl_xor_sync(0xffffffffu, sq, 2);
        sq += __shfl_xor_sync(0xffffffffu, sq, 4);
        if (seg == 0) nsq[r] = 0.5f * sq;
    }
    __syncthreads();

    // projection: thread owns column f
#pragma unroll 2
    for (int r = 0; r < TS_OUT; r++) phi[r][f] = proj_row(qs[r], w2);
    __syncthreads();

    // per-row max over f
    {
        const int r = threadIdx.x >> 3, part = threadIdx.x & 7;
        float m = -3.0e38f;
        const float* pr = &phi[r][part * 32];
#pragma unroll
        for (int i = 0; i < 32; i++) m = fmaxf(m, pr[i]);
        m = fmaxf(m, __shfl_xor_sync(0xffffffffu, m, 1));
        m = fmaxf(m, __shfl_xor_sync(0xffffffffu, m, 2));
        m = fmaxf(m, __shfl_xor_sync(0xffffffffu, m, 4));
        if (part == 0) mrow[r] = m;
    }
    __syncthreads();

    // exp in place
#pragma unroll 4
    for (int r = 0; r < TS_OUT; r++)
        phi[r][f] = __expf(phi[r][f] - nsq[r] - mrow[r]) * INV_SQRT_F;
    __syncthreads();

    // deno[r] = max(sum_f phi[r][f]*ksum[f], 1e-4)
    {
        const int r = threadIdx.x >> 3, part = threadIdx.x & 7;
        float s = 0.0f;
        const float* pr = &phi[r][part * 32];
        const float* ks = &ksum_s[part * 32];
#pragma unroll
        for (int i = 0; i < 32; i++) s += pr[i] * ks[i];
        s += __shfl_xor_sync(0xffffffffu, s, 1);
        s += __shfl_xor_sync(0xffffffffu, s, 2);
        s += __shfl_xor_sync(0xffffffffu, s, 4);
        if (part == 0) dens[r] = fmaxf(s, 1e-4f);
    }

    // out tile: thread owns 2 rows x 4 d
    const int rg = threadIdx.x >> 4;   // 0..15
    const int dg = threadIdx.x & 15;   // d = dg*4
    const int r0 = rg * 2, r1 = rg * 2 + 1;
    u64 acc00 = 0ull, acc01 = 0ull, acc10 = 0ull, acc11 = 0ull;
    for (int fc = 0; fc < FF / 16; fc++) {
        {
            const int fr = threadIdx.x >> 4, seg = threadIdx.x & 15;
            *(float4*)&kvs[fr][seg * 4] =
                *(const float4*)(g_kv + (b * FF + fc * 16 + fr) * DD + seg * 4);
        }
        __syncthreads();
#pragma unroll
        for (int ff = 0; ff < 16; ff++) {
            float p0v = phi[r0][fc * 16 + ff];
            float p1v = phi[r1][fc * 16 + ff];
            ulonglong2 kk = *(const ulonglong2*)&kvs[ff][dg * 4];
            u64 p02 = pk2(p0v, p0v), p12 = pk2(p1v, p1v);
            acc00 = fma2(p02, kk.x, acc00);
            acc01 = fma2(p02, kk.y, acc01);
            acc10 = fma2(p12, kk.x, acc10);
            acc11 = fma2(p12, kk.y, acc11);
        }
        __syncthreads();
    }
    const float inv0 = 1.0f / dens[r0];
    const float inv1 = 1.0f / dens[r1];
    float2 a0 = upk2(acc00), a1 = upk2(acc01);
    float2 b0 = upk2(acc10), b1 = upk2(acc11);
    float4 o0 = make_float4(a0.x * inv0, a0.y * inv0, a1.x * inv0, a1.y * inv0);
    float4 o1 = make_float4(b0.x * inv1, b0.y * inv1, b1.x * inv1, b1.y * inv1);
    *(float4*)(out + (b * SS + tile * TS_OUT + r0) * DD + dg * 4) = o0;
    *(float4*)(out + (b * SS + tile * TS_OUT + r1) * DD + dg * 4) = o1;
}

// ---------------- launch ----------------------------------------------------
extern "C" void kernel_launch(void* const* d_in, const int* in_sizes, int n_in,
                              void* d_out, int out_size) {
    const float* q = (const float*)d_in[0];
    const float* k = (const float*)d_in[1];
    const float* v = (const float*)d_in[2];
    const float* w = (const float*)d_in[3];
    float* out = (float*)d_out;

    init_kernel<<<(BB * FF * DD + 255) / 256, 256>>>();
    mean_kernel<<<dim3(BB, 4), 256>>>(k);
    kmax_kernel<<<dim3(BB, SS / TS_KM), 256>>>(k, w);
    kv_kernel<<<dim3(BB, SS / TS_KV), 256>>>(k, v, w);
    out_kernel<<<dim3(BB, SS / TS_OUT), 256>>>(q, w, out);
}